// round 8
// baseline (speedup 1.0000x reference)
#include <cuda_runtime.h>
#include <cuda_fp16.h>
#include <cstddef>

#define NUC 100000
#define NIC 50000
#define DC 64
#define EBC 500000
#define ECC 1000000
#define EPC 2000000
#define ETOT (EBC + ECC + EPC)
#define WPB 8     // warps per block
#define NPW 8     // nodes per warp

// ---------------- scratch (device globals; no allocation allowed) ----------
__device__ float g_srcB[NUC * DC];          // fp32 atomic accumulation (L0 result)
__device__ float g_dstB[NIC * DC];
__device__ __half g_srcH[NUC * DC];         // half copy for L1 gathers
__device__ __half g_dstH[NIC * DC];
__device__ __half g_embUH[NUC * DC];        // half copies of input embeddings
__device__ __half g_embVH[NIC * DC];
__device__ __half g_se[3][NUC * DC];        // layer-0 (sum_e w) @ We, u-side (half)
__device__ __half g_de[3][NIC * DC];        // v-side (half)
__device__ int g_cntU[3 * NUC];
__device__ int g_cntV[3 * NIC];
__device__ int g_rowU[3 * (NUC + 1)];
__device__ int g_rowV[3 * (NIC + 1)];
__device__ int g_curU[3 * NUC];
__device__ int g_curV[3 * NIC];
__device__ float2 g_drU[3 * NUC];           // {deg, rsqrt(deg)}
__device__ float2 g_drV[3 * NIC];
__device__ int2 g_adjU[ETOT];               // {edge id, opposite node}
__device__ int2 g_adjV[ETOT];

__device__ __forceinline__ float lk(float x) { return x >= 0.f ? x : 0.01f * x; }

__device__ __forceinline__ float4 h4tof4(uint2 u) {
    __half2 a = *(__half2*)&u.x;
    __half2 b = *(__half2*)&u.y;
    float2 fa = __half22float2(a), fb = __half22float2(b);
    return make_float4(fa.x, fa.y, fb.x, fb.y);
}
__device__ __forceinline__ uint2 f4toh4(float4 v) {
    __half2 a = __float22half2_rn(make_float2(v.x, v.y));
    __half2 b = __float22half2_rn(make_float2(v.z, v.w));
    uint2 u;
    u.x = *(unsigned*)&a;
    u.y = *(unsigned*)&b;
    return u;
}

// ---------------- setup kernels --------------------------------------------

// out = in * s (output accumulator init, pre-scaled by final 1/(L+1))
__global__ void k_init(const float4* __restrict__ in, float s,
                       float4* __restrict__ out, int n4) {
    int i = blockIdx.x * blockDim.x + threadIdx.x;
    if (i < n4) {
        float4 v = in[i];
        out[i] = make_float4(v.x * s, v.y * s, v.z * s, v.w * s);
    }
}

__global__ void k_tohalf(const float4* __restrict__ in, uint2* __restrict__ out, int n4) {
    int i = blockIdx.x * blockDim.x + threadIdx.x;
    if (i < n4) out[i] = f4toh4(in[i]);
}

__global__ void k_hist(const int* __restrict__ U, const int* __restrict__ V, int E,
                       int* __restrict__ cU, int* __restrict__ cV) {
    int i = blockIdx.x * blockDim.x + threadIdx.x;
    if (i < E) {
        atomicAdd(cU + U[i], 1);
        atomicAdd(cV + V[i], 1);
    }
}

__global__ void k_deg(const int* __restrict__ cnt, float2* __restrict__ dr, int n) {
    int i = blockIdx.x * blockDim.x + threadIdx.x;
    if (i < n) {
        float d = (float)(cnt[i] < 1 ? 1 : cnt[i]);
        dr[i] = make_float2(d, rsqrtf(d));
    }
}

// 6 blocks: block b handles (side=b/3, type=b%3). Exclusive scan of counts.
__global__ void k_scan6(const int* __restrict__ cntU, const int* __restrict__ cntV,
                        int* __restrict__ rowU, int* __restrict__ rowV,
                        int* __restrict__ curU, int* __restrict__ curV) {
    __shared__ int ssum[1024];
    int b = blockIdx.x, side = b / 3, t = b % 3;
    const int* cnt; int* row; int* cur; int n;
    if (side == 0) { n = NUC; cnt = cntU + t * NUC; row = rowU + t * (NUC + 1); cur = curU + t * NUC; }
    else           { n = NIC; cnt = cntV + t * NIC; row = rowV + t * (NIC + 1); cur = curV + t * NIC; }
    int tid = threadIdx.x;
    int chunk = (n + 1023) / 1024;
    int lo = tid * chunk; if (lo > n) lo = n;
    int hi = lo + chunk; if (hi > n) hi = n;
    int s = 0;
    for (int i = lo; i < hi; i++) s += cnt[i];
    ssum[tid] = s;
    __syncthreads();
    for (int off = 1; off < 1024; off <<= 1) {
        int v = (tid >= off) ? ssum[tid - off] : 0;
        __syncthreads();
        ssum[tid] += v;
        __syncthreads();
    }
    int run = (tid == 0) ? 0 : ssum[tid - 1];
    for (int i = lo; i < hi; i++) {
        row[i] = run; cur[i] = run;
        run += cnt[i];
    }
    if (hi == n) row[n] = run;
}

__global__ void k_fill(const int* __restrict__ U, const int* __restrict__ V, int E,
                       int* __restrict__ cU, int* __restrict__ cV,
                       int2* __restrict__ adjU, int2* __restrict__ adjV) {
    int e = blockIdx.x * blockDim.x + threadIdx.x;
    if (e < E) {
        int u = U[e], v = V[e];
        int pu = atomicAdd(cU + u, 1);
        adjU[pu] = make_int2(e, v);
        int pv = atomicAdd(cV + v, 1);
        adjV[pv] = make_int2(e, u);
    }
}

// ---------------- layer 0: gather + fused dual matmul -----------------------
// gridDim.y = edge type t. Per node: warp gathers agg = sum_e f[opp]*rs*A*w and
// b = sum_e w (w = B*edge_feat). Then half 0 computes agg@Wn (gconv epilogue,
// atomic accumulate into nxt & out), half 1 computes b@We (-> se half store).
__global__ void __launch_bounds__(WPB * 32) k_l0(
        const float* __restrict__ e0, const float* __restrict__ e1,
        const float* __restrict__ e2,
        const int2* __restrict__ adjAll, const int* __restrict__ rowAll,
        int rowStride,
        const __half* __restrict__ oppEmb, float oppScale,
        const float2* __restrict__ drOppAll, int nOpp,
        const float2* __restrict__ drMyAll,
        const float* __restrict__ Wn, const float* __restrict__ We,
        float* __restrict__ nxt, __half* __restrict__ seOut,
        float* __restrict__ outp, int n) {
    int t = blockIdx.y;
    const float* ew = (t == 0) ? e0 : (t == 1 ? e1 : e2);
    size_t eoff = (t > 0 ? (size_t)EBC : 0) + (t > 1 ? (size_t)ECC : 0);
    const int2* adj = adjAll + eoff;
    const int* row = rowAll + t * rowStride;
    const float2* drOpp = drOppAll + t * nOpp;
    const float2* drMy = drMyAll + t * n;
    __half* se = seOut + (size_t)t * n * DC;
    float wgt = (t == 0) ? 1.f : (t == 1 ? 0.5f : 0.25f);
    const float Bsc = 0.0045f;

    __shared__ float4 sWn[64 * 16];
    __shared__ float4 sWe[64 * 16];
    __shared__ float4 wrow4[WPB][34];   // a: [0..15], b: [17..32]

    int tid = threadIdx.x;
    for (int i = tid; i < 1024; i += WPB * 32) {
        sWn[i] = ((const float4*)Wn)[i];
        sWe[i] = ((const float4*)We)[i];
    }
    __syncthreads();

    int wid = tid >> 5, lane = tid & 31, l16 = lane & 15, half = lane >> 4;
    int nodeBase = (blockIdx.x * WPB + wid) * NPW;

    for (int nd = 0; nd < NPW; nd++) {
        int node = nodeBase + nd;
        if (node >= n) break;   // warp-uniform
        int s0 = row[node], s1 = row[node + 1];
        float4 a = make_float4(0.f, 0.f, 0.f, 0.f);
        float4 b = make_float4(0.f, 0.f, 0.f, 0.f);
#pragma unroll 2
        for (int i = s0 + half; i < s1; i += 2) {
            int2 ad = __ldg(adj + i);
            float4 w = __ldg((const float4*)(ew + (size_t)ad.x * DC) + l16);
            w.x *= Bsc; w.y *= Bsc; w.z *= Bsc; w.w *= Bsc;
            float r = __ldg(drOpp + ad.y).y * oppScale;
            float4 f = h4tof4(__ldg((const uint2*)(oppEmb + (size_t)ad.y * DC) + l16));
            b.x += w.x; b.y += w.y; b.z += w.z; b.w += w.w;
            a.x += f.x * r * w.x; a.y += f.y * r * w.y;
            a.z += f.z * r * w.z; a.w += f.w * r * w.w;
        }
        a.x += __shfl_xor_sync(0xffffffffu, a.x, 16);
        a.y += __shfl_xor_sync(0xffffffffu, a.y, 16);
        a.z += __shfl_xor_sync(0xffffffffu, a.z, 16);
        a.w += __shfl_xor_sync(0xffffffffu, a.w, 16);
        b.x += __shfl_xor_sync(0xffffffffu, b.x, 16);
        b.y += __shfl_xor_sync(0xffffffffu, b.y, 16);
        b.z += __shfl_xor_sync(0xffffffffu, b.z, 16);
        b.w += __shfl_xor_sync(0xffffffffu, b.w, 16);
        if (half == 0) wrow4[wid][l16] = a;
        else           wrow4[wid][17 + l16] = b;
        __syncwarp();

        // dual matmul: half 0 -> a @ Wn ; half 1 -> b @ We
        const float* rsel = (const float*)&wrow4[wid][0] + (half ? 68 : 0);
        const float4* Wsel = half ? sWe : sWn;
        float4 acc = make_float4(0.f, 0.f, 0.f, 0.f);
#pragma unroll
        for (int d = 0; d < 64; d++) {
            float s = rsel[d];
            float4 w4 = Wsel[d * 16 + l16];
            acc.x += s * w4.x; acc.y += s * w4.y;
            acc.z += s * w4.z; acc.w += s * w4.w;
        }
        __syncwarp();
        if (half == 0) {
            float rsn = drMy[node].y;
            float4 res;
            res.x = lk(acc.x * rsn) * wgt;
            res.y = lk(acc.y * rsn) * wgt;
            res.z = lk(acc.z * rsn) * wgt;
            res.w = lk(acc.w * rsn) * wgt;
            size_t off = (size_t)node * DC + l16 * 4;
            atomicAdd((float4*)(nxt + off), res);
            float4 ro = make_float4(res.x * (1.f / 3.f), res.y * (1.f / 3.f),
                                    res.z * (1.f / 3.f), res.w * (1.f / 3.f));
            atomicAdd((float4*)(outp + off), ro);
        } else {
            ((uint2*)(se + (size_t)node * DC))[l16] = f4toh4(acc);
        }
    }
}

// ---------------- layer 1: on-the-fly edge weights + fused matmul -----------
// w_e = leaky((seW[my] + deW[opp]) / (deg[my] + deg[opp])); agg = sum f*r*w.
// All gathered streams fp16; matmul split across halves then shfl-combined.
__global__ void __launch_bounds__(WPB * 32) k_l1(
        const int2* __restrict__ adjAll, const int* __restrict__ rowAll,
        int rowStride,
        const __half* __restrict__ myDeWAll, const __half* __restrict__ oppDeWAll,
        const float2* __restrict__ drMyAll, const float2* __restrict__ drOppAll,
        const __half* __restrict__ oppF, int nOpp,
        const float* __restrict__ Wn, float* __restrict__ outp, int n) {
    int t = blockIdx.y;
    size_t eoff = (t > 0 ? (size_t)EBC : 0) + (t > 1 ? (size_t)ECC : 0);
    const int2* adj = adjAll + eoff;
    const int* row = rowAll + t * rowStride;
    const __half* myDeW = myDeWAll + (size_t)t * n * DC;
    const __half* oppDeW = oppDeWAll + (size_t)t * nOpp * DC;
    const float2* drMy = drMyAll + t * n;
    const float2* drOpp = drOppAll + t * nOpp;
    float wgt = (t == 0) ? 1.f : (t == 1 ? 0.5f : 0.25f);

    __shared__ float4 sWn[64 * 16];
    __shared__ float wrow[WPB][66];   // a[d] at index d + (d>>5)

    int tid = threadIdx.x;
    for (int i = tid; i < 1024; i += WPB * 32) sWn[i] = ((const float4*)Wn)[i];
    __syncthreads();

    int wid = tid >> 5, lane = tid & 31, l16 = lane & 15, half = lane >> 4;
    int nodeBase = (blockIdx.x * WPB + wid) * NPW;

    for (int nd = 0; nd < NPW; nd++) {
        int node = nodeBase + nd;
        if (node >= n) break;
        int s0 = row[node], s1 = row[node + 1];
        float md = drMy[node].x;
        float4 m = h4tof4(__ldg((const uint2*)(myDeW + (size_t)node * DC) + l16));
        float4 a = make_float4(0.f, 0.f, 0.f, 0.f);
#pragma unroll 2
        for (int i = s0 + half; i < s1; i += 2) {
            int2 ad = __ldg(adj + i);
            float2 dro = __ldg(drOpp + ad.y);
            float s = 1.f / (md + dro.x);
            float4 o = h4tof4(__ldg((const uint2*)(oppDeW + (size_t)ad.y * DC) + l16));
            float4 f = h4tof4(__ldg((const uint2*)(oppF + (size_t)ad.y * DC) + l16));
            float r = dro.y;
            float wx = lk((m.x + o.x) * s);
            float wy = lk((m.y + o.y) * s);
            float wz = lk((m.z + o.z) * s);
            float ww = lk((m.w + o.w) * s);
            a.x += f.x * r * wx; a.y += f.y * r * wy;
            a.z += f.z * r * wz; a.w += f.w * r * ww;
        }
        a.x += __shfl_xor_sync(0xffffffffu, a.x, 16);
        a.y += __shfl_xor_sync(0xffffffffu, a.y, 16);
        a.z += __shfl_xor_sync(0xffffffffu, a.z, 16);
        a.w += __shfl_xor_sync(0xffffffffu, a.w, 16);
        if (half == 0) {
            int p = l16 * 4;
            wrow[wid][p + (p >> 5)] = a.x;
            wrow[wid][p + 1 + ((p + 1) >> 5)] = a.y;
            wrow[wid][p + 2 + ((p + 2) >> 5)] = a.z;
            wrow[wid][p + 3 + ((p + 3) >> 5)] = a.w;
        }
        __syncwarp();

        const float* wr = &wrow[wid][half * 33];
        const float4* Wh = sWn + half * 32 * 16;
        float4 acc = make_float4(0.f, 0.f, 0.f, 0.f);
#pragma unroll
        for (int d2 = 0; d2 < 32; d2++) {
            float s = wr[d2];
            float4 w4 = Wh[d2 * 16 + l16];
            acc.x += s * w4.x; acc.y += s * w4.y;
            acc.z += s * w4.z; acc.w += s * w4.w;
        }
        acc.x += __shfl_xor_sync(0xffffffffu, acc.x, 16);
        acc.y += __shfl_xor_sync(0xffffffffu, acc.y, 16);
        acc.z += __shfl_xor_sync(0xffffffffu, acc.z, 16);
        acc.w += __shfl_xor_sync(0xffffffffu, acc.w, 16);
        __syncwarp();
        if (half == 0) {
            float rsn = drMy[node].y;
            float c = wgt * (1.f / 3.f);
            float4 ro;
            ro.x = lk(acc.x * rsn) * c;
            ro.y = lk(acc.y * rsn) * c;
            ro.z = lk(acc.z * rsn) * c;
            ro.w = lk(acc.w * rsn) * c;
            atomicAdd((float4*)(outp + (size_t)node * DC + l16 * 4), ro);
        }
    }
}

// ---------------- host orchestration ---------------------------------------
extern "C" void kernel_launch(void* const* d_in, const int* in_sizes, int n_in,
                              void* d_out, int out_size) {
    const float* user_emb = (const float*)d_in[0];
    const float* item_emb = (const float*)d_in[1];
    const float* e0 = (const float*)d_in[2];
    const float* e1 = (const float*)d_in[3];
    const float* e2 = (const float*)d_in[4];
    const float* nodeW = (const float*)d_in[5];
    const float* edgeW = (const float*)d_in[6];
    const int* Ua[3] = {(const int*)d_in[7], (const int*)d_in[9], (const int*)d_in[11]};
    const int* Va[3] = {(const int*)d_in[8], (const int*)d_in[10], (const int*)d_in[12]};
    float* out = (float*)d_out;
    float* outS = out;
    float* outD = out + (size_t)NUC * DC;

    float *srcB, *dstB;
    __half *srcH, *dstH, *embUH, *embVH, *se, *de;
    int *cntU, *cntV, *rowU, *rowV, *curU, *curV;
    float2 *drU, *drV;
    int2 *adjU, *adjV;
    cudaGetSymbolAddress((void**)&srcB, g_srcB);
    cudaGetSymbolAddress((void**)&dstB, g_dstB);
    cudaGetSymbolAddress((void**)&srcH, g_srcH);
    cudaGetSymbolAddress((void**)&dstH, g_dstH);
    cudaGetSymbolAddress((void**)&embUH, g_embUH);
    cudaGetSymbolAddress((void**)&embVH, g_embVH);
    cudaGetSymbolAddress((void**)&se, g_se);
    cudaGetSymbolAddress((void**)&de, g_de);
    cudaGetSymbolAddress((void**)&cntU, g_cntU);
    cudaGetSymbolAddress((void**)&cntV, g_cntV);
    cudaGetSymbolAddress((void**)&rowU, g_rowU);
    cudaGetSymbolAddress((void**)&rowV, g_rowV);
    cudaGetSymbolAddress((void**)&curU, g_curU);
    cudaGetSymbolAddress((void**)&curV, g_curV);
    cudaGetSymbolAddress((void**)&drU, g_drU);
    cudaGetSymbolAddress((void**)&drV, g_drV);
    cudaGetSymbolAddress((void**)&adjU, g_adjU);
    cudaGetSymbolAddress((void**)&adjV, g_adjV);

    const int Ecnt[3] = {EBC, ECC, EPC};
    const float Asc = 0.0045f;
    const float* Wn0 = nodeW;
    const float* Wn1 = nodeW + (size_t)DC * DC;
    const float* We0 = edgeW;

    // output accumulator init (pre-scaled by 1/3), half embeddings, zero nxt
    k_init<<<(NUC * DC / 4 + 255) / 256, 256>>>((const float4*)user_emb,
                                                Asc / 3.f, (float4*)outS, NUC * DC / 4);
    k_init<<<(NIC * DC / 4 + 255) / 256, 256>>>((const float4*)item_emb,
                                                Asc / 3.f, (float4*)outD, NIC * DC / 4);
    k_tohalf<<<(NUC * DC / 4 + 255) / 256, 256>>>((const float4*)user_emb,
                                                  (uint2*)embUH, NUC * DC / 4);
    k_tohalf<<<(NIC * DC / 4 + 255) / 256, 256>>>((const float4*)item_emb,
                                                  (uint2*)embVH, NIC * DC / 4);
    cudaMemsetAsync(srcB, 0, (size_t)NUC * DC * sizeof(float));
    cudaMemsetAsync(dstB, 0, (size_t)NIC * DC * sizeof(float));

    // CSR build
    cudaMemsetAsync(cntU, 0, 3 * NUC * sizeof(int));
    cudaMemsetAsync(cntV, 0, 3 * NIC * sizeof(int));
    for (int t = 0; t < 3; t++)
        k_hist<<<(Ecnt[t] + 255) / 256, 256>>>(Ua[t], Va[t], Ecnt[t],
                                               cntU + t * NUC, cntV + t * NIC);
    k_deg<<<(3 * NUC + 255) / 256, 256>>>(cntU, drU, 3 * NUC);
    k_deg<<<(3 * NIC + 255) / 256, 256>>>(cntV, drV, 3 * NIC);
    k_scan6<<<6, 1024>>>(cntU, cntV, rowU, rowV, curU, curV);
    {
        size_t eo = 0;
        for (int t = 0; t < 3; t++) {
            k_fill<<<(Ecnt[t] + 255) / 256, 256>>>(Ua[t], Va[t], Ecnt[t],
                                                   curU + t * NUC, curV + t * NIC,
                                                   adjU + eo, adjV + eo);
            eo += Ecnt[t];
        }
    }

    // layer 0 (3 types concurrent via gridDim.y)
    {
        dim3 gu((NUC + WPB * NPW - 1) / (WPB * NPW), 3);
        dim3 gv((NIC + WPB * NPW - 1) / (WPB * NPW), 3);
        k_l0<<<gu, WPB * 32>>>(e0, e1, e2, adjU, rowU, NUC + 1,
                               embVH, Asc, drV, NIC, drU,
                               Wn0, We0, srcB, se, outS, NUC);
        k_l0<<<gv, WPB * 32>>>(e0, e1, e2, adjV, rowV, NIC + 1,
                               embUH, Asc, drU, NUC, drV,
                               Wn0, We0, dstB, de, outD, NIC);
    }

    // convert L0 node results to half for L1 gathers
    k_tohalf<<<(NUC * DC / 4 + 255) / 256, 256>>>((const float4*)srcB,
                                                  (uint2*)srcH, NUC * DC / 4);
    k_tohalf<<<(NIC * DC / 4 + 255) / 256, 256>>>((const float4*)dstB,
                                                  (uint2*)dstH, NIC * DC / 4);

    // layer 1 (edge features recomputed on the fly; fp16 gather streams)
    {
        dim3 gu((NUC + WPB * NPW - 1) / (WPB * NPW), 3);
        dim3 gv((NIC + WPB * NPW - 1) / (WPB * NPW), 3);
        k_l1<<<gu, WPB * 32>>>(adjU, rowU, NUC + 1, se, de, drU, drV,
                               dstH, NIC, Wn1, outS, NUC);
        k_l1<<<gv, WPB * 32>>>(adjV, rowV, NIC + 1, de, se, drV, drU,
                               srcH, NUC, Wn1, outD, NIC);
    }
}

// round 9
// speedup vs baseline: 1.5162x; 1.5162x over previous
#include <cuda_runtime.h>
#include <cstddef>

#define NUC 100000
#define NIC 50000
#define DC 64
#define EBC 500000
#define ECC 1000000
#define EPC 2000000
#define ETOT (EBC + ECC + EPC)
#define WPB 8     // warps per block
#define NPW 8     // nodes per warp

// ---------------- scratch (device globals; no allocation allowed) ----------
__device__ float g_srcB[NUC * DC];
__device__ float g_dstB[NIC * DC];
__device__ float g_se[3][NUC * DC];   // layer-0 (sum_e w) @ We, u-side
__device__ float g_de[3][NIC * DC];   // layer-0 (sum_e w) @ We, v-side
__device__ int g_cntU[3 * NUC];
__device__ int g_cntV[3 * NIC];
__device__ int g_rowU[3 * (NUC + 1)];
__device__ int g_rowV[3 * (NIC + 1)];
__device__ int g_curU[3 * NUC];
__device__ int g_curV[3 * NIC];
__device__ float2 g_drU[3 * NUC];     // {deg, rsqrt(deg)}
__device__ float2 g_drV[3 * NIC];
__device__ int2 g_adjU[ETOT];         // {edge id, opposite node}
__device__ int2 g_adjV[ETOT];

__device__ __forceinline__ float lk(float x) { return x >= 0.f ? x : 0.01f * x; }

// ---------------- setup kernels --------------------------------------------

// out = in * s (output accumulator init, pre-scaled by final 1/(L+1))
__global__ void k_init(const float4* __restrict__ in, float s,
                       float4* __restrict__ out, int n4) {
    int i = blockIdx.x * blockDim.x + threadIdx.x;
    if (i < n4) {
        float4 v = in[i];
        out[i] = make_float4(v.x * s, v.y * s, v.z * s, v.w * s);
    }
}

__global__ void k_hist(const int* __restrict__ U, const int* __restrict__ V, int E,
                       int* __restrict__ cU, int* __restrict__ cV) {
    int i = blockIdx.x * blockDim.x + threadIdx.x;
    if (i < E) {
        atomicAdd(cU + U[i], 1);
        atomicAdd(cV + V[i], 1);
    }
}

__global__ void k_deg(const int* __restrict__ cnt, float2* __restrict__ dr, int n) {
    int i = blockIdx.x * blockDim.x + threadIdx.x;
    if (i < n) {
        float d = (float)(cnt[i] < 1 ? 1 : cnt[i]);
        dr[i] = make_float2(d, rsqrtf(d));
    }
}

// 6 blocks: block b handles (side=b/3, type=b%3). Exclusive scan of counts.
__global__ void k_scan6(const int* __restrict__ cntU, const int* __restrict__ cntV,
                        int* __restrict__ rowU, int* __restrict__ rowV,
                        int* __restrict__ curU, int* __restrict__ curV) {
    __shared__ int ssum[1024];
    int b = blockIdx.x, side = b / 3, t = b % 3;
    const int* cnt; int* row; int* cur; int n;
    if (side == 0) { n = NUC; cnt = cntU + t * NUC; row = rowU + t * (NUC + 1); cur = curU + t * NUC; }
    else           { n = NIC; cnt = cntV + t * NIC; row = rowV + t * (NIC + 1); cur = curV + t * NIC; }
    int tid = threadIdx.x;
    int chunk = (n + 1023) / 1024;
    int lo = tid * chunk; if (lo > n) lo = n;
    int hi = lo + chunk; if (hi > n) hi = n;
    int s = 0;
    for (int i = lo; i < hi; i++) s += cnt[i];
    ssum[tid] = s;
    __syncthreads();
    for (int off = 1; off < 1024; off <<= 1) {
        int v = (tid >= off) ? ssum[tid - off] : 0;
        __syncthreads();
        ssum[tid] += v;
        __syncthreads();
    }
    int run = (tid == 0) ? 0 : ssum[tid - 1];
    for (int i = lo; i < hi; i++) {
        row[i] = run; cur[i] = run;
        run += cnt[i];
    }
    if (hi == n) row[n] = run;
}

__global__ void k_fill(const int* __restrict__ U, const int* __restrict__ V, int E,
                       int* __restrict__ cU, int* __restrict__ cV,
                       int2* __restrict__ adjU, int2* __restrict__ adjV) {
    int e = blockIdx.x * blockDim.x + threadIdx.x;
    if (e < E) {
        int u = U[e], v = V[e];
        int pu = atomicAdd(cU + u, 1);
        adjU[pu] = make_int2(e, v);
        int pv = atomicAdd(cV + v, 1);
        adjV[pv] = make_int2(e, u);
    }
}

// ---------------- layer 0: gather + fused dual matmul -----------------------
// gridDim.y = edge type t. Per node: warp gathers agg = sum_e f[opp]*rs*A*w and
// b = sum_e w. Half 0 computes agg@Wn (epilogue -> atomics), half 1 b@We (-> se).
// Inner loop: explicit 4-edge batch per half for memory-level parallelism.
__global__ void __launch_bounds__(WPB * 32) k_l0(
        const float* __restrict__ e0, const float* __restrict__ e1,
        const float* __restrict__ e2,
        const int2* __restrict__ adjAll, const int* __restrict__ rowAll,
        int rowStride,
        const float* __restrict__ oppEmb, float oppScale,
        const float2* __restrict__ drOppAll, int nOpp,
        const float2* __restrict__ drMyAll,
        const float* __restrict__ Wn, const float* __restrict__ We,
        float* __restrict__ nxt, float* __restrict__ seOut,
        float* __restrict__ outp, int n) {
    int t = blockIdx.y;
    const float* ew = (t == 0) ? e0 : (t == 1 ? e1 : e2);
    size_t eoff = (t > 0 ? (size_t)EBC : 0) + (t > 1 ? (size_t)ECC : 0);
    const int2* adj = adjAll + eoff;
    const int* row = rowAll + t * rowStride;
    const float2* drOpp = drOppAll + t * nOpp;
    const float2* drMy = drMyAll + t * n;
    float* se = seOut + (size_t)t * n * DC;
    float wgt = (t == 0) ? 1.f : (t == 1 ? 0.5f : 0.25f);
    const float Bsc = 0.0045f;

    __shared__ float4 sWn[64 * 16];
    __shared__ float4 sWe[64 * 16];
    __shared__ float4 wrow4[WPB][34];   // a: [0..15], b: [17..32]

    int tid = threadIdx.x;
    for (int i = tid; i < 1024; i += WPB * 32) {
        sWn[i] = ((const float4*)Wn)[i];
        sWe[i] = ((const float4*)We)[i];
    }
    __syncthreads();

    int wid = tid >> 5, lane = tid & 31, l16 = lane & 15, half = lane >> 4;
    int nodeBase = (blockIdx.x * WPB + wid) * NPW;

    for (int nd = 0; nd < NPW; nd++) {
        int node = nodeBase + nd;
        if (node >= n) break;   // warp-uniform
        int s0 = row[node], s1 = row[node + 1];
        float4 a = make_float4(0.f, 0.f, 0.f, 0.f);
        float4 b = make_float4(0.f, 0.f, 0.f, 0.f);
        int i = s0 + half;
        // main loop: 4 edges per half in flight (12 gather LDGs batched)
        for (; i + 6 < s1; i += 8) {
            int2 ad0 = __ldg(adj + i);
            int2 ad1 = __ldg(adj + i + 2);
            int2 ad2 = __ldg(adj + i + 4);
            int2 ad3 = __ldg(adj + i + 6);
            float4 w0 = __ldg((const float4*)(ew + (size_t)ad0.x * DC) + l16);
            float4 w1 = __ldg((const float4*)(ew + (size_t)ad1.x * DC) + l16);
            float4 w2 = __ldg((const float4*)(ew + (size_t)ad2.x * DC) + l16);
            float4 w3 = __ldg((const float4*)(ew + (size_t)ad3.x * DC) + l16);
            float4 f0 = __ldg((const float4*)(oppEmb + (size_t)ad0.y * DC) + l16);
            float4 f1 = __ldg((const float4*)(oppEmb + (size_t)ad1.y * DC) + l16);
            float4 f2 = __ldg((const float4*)(oppEmb + (size_t)ad2.y * DC) + l16);
            float4 f3 = __ldg((const float4*)(oppEmb + (size_t)ad3.y * DC) + l16);
            float r0 = __ldg(drOpp + ad0.y).y * oppScale;
            float r1 = __ldg(drOpp + ad1.y).y * oppScale;
            float r2 = __ldg(drOpp + ad2.y).y * oppScale;
            float r3 = __ldg(drOpp + ad3.y).y * oppScale;
            w0.x *= Bsc; w0.y *= Bsc; w0.z *= Bsc; w0.w *= Bsc;
            w1.x *= Bsc; w1.y *= Bsc; w1.z *= Bsc; w1.w *= Bsc;
            w2.x *= Bsc; w2.y *= Bsc; w2.z *= Bsc; w2.w *= Bsc;
            w3.x *= Bsc; w3.y *= Bsc; w3.z *= Bsc; w3.w *= Bsc;
            b.x += w0.x + w1.x + w2.x + w3.x;
            b.y += w0.y + w1.y + w2.y + w3.y;
            b.z += w0.z + w1.z + w2.z + w3.z;
            b.w += w0.w + w1.w + w2.w + w3.w;
            a.x += f0.x * r0 * w0.x + f1.x * r1 * w1.x + f2.x * r2 * w2.x + f3.x * r3 * w3.x;
            a.y += f0.y * r0 * w0.y + f1.y * r1 * w1.y + f2.y * r2 * w2.y + f3.y * r3 * w3.y;
            a.z += f0.z * r0 * w0.z + f1.z * r1 * w1.z + f2.z * r2 * w2.z + f3.z * r3 * w3.z;
            a.w += f0.w * r0 * w0.w + f1.w * r1 * w1.w + f2.w * r2 * w2.w + f3.w * r3 * w3.w;
        }
        // remainder
        for (; i < s1; i += 2) {
            int2 ad = __ldg(adj + i);
            float4 w = __ldg((const float4*)(ew + (size_t)ad.x * DC) + l16);
            float r = __ldg(drOpp + ad.y).y * oppScale;
            float4 f = __ldg((const float4*)(oppEmb + (size_t)ad.y * DC) + l16);
            w.x *= Bsc; w.y *= Bsc; w.z *= Bsc; w.w *= Bsc;
            b.x += w.x; b.y += w.y; b.z += w.z; b.w += w.w;
            a.x += f.x * r * w.x; a.y += f.y * r * w.y;
            a.z += f.z * r * w.z; a.w += f.w * r * w.w;
        }
        a.x += __shfl_xor_sync(0xffffffffu, a.x, 16);
        a.y += __shfl_xor_sync(0xffffffffu, a.y, 16);
        a.z += __shfl_xor_sync(0xffffffffu, a.z, 16);
        a.w += __shfl_xor_sync(0xffffffffu, a.w, 16);
        b.x += __shfl_xor_sync(0xffffffffu, b.x, 16);
        b.y += __shfl_xor_sync(0xffffffffu, b.y, 16);
        b.z += __shfl_xor_sync(0xffffffffu, b.z, 16);
        b.w += __shfl_xor_sync(0xffffffffu, b.w, 16);
        if (half == 0) wrow4[wid][l16] = a;
        else           wrow4[wid][17 + l16] = b;
        __syncwarp();

        // dual matmul: half 0 -> a @ Wn ; half 1 -> b @ We
        const float* rsel = (const float*)&wrow4[wid][0] + (half ? 68 : 0);
        const float4* Wsel = half ? sWe : sWn;
        float4 acc = make_float4(0.f, 0.f, 0.f, 0.f);
#pragma unroll
        for (int d = 0; d < 64; d++) {
            float s = rsel[d];
            float4 w4 = Wsel[d * 16 + l16];
            acc.x += s * w4.x; acc.y += s * w4.y;
            acc.z += s * w4.z; acc.w += s * w4.w;
        }
        __syncwarp();
        if (half == 0) {
            float rsn = drMy[node].y;
            float4 res;
            res.x = lk(acc.x * rsn) * wgt;
            res.y = lk(acc.y * rsn) * wgt;
            res.z = lk(acc.z * rsn) * wgt;
            res.w = lk(acc.w * rsn) * wgt;
            size_t off = (size_t)node * DC + l16 * 4;
            atomicAdd((float4*)(nxt + off), res);
            float4 ro = make_float4(res.x * (1.f / 3.f), res.y * (1.f / 3.f),
                                    res.z * (1.f / 3.f), res.w * (1.f / 3.f));
            atomicAdd((float4*)(outp + off), ro);
        } else {
            ((float4*)(se + (size_t)node * DC))[l16] = acc;
        }
    }
}

// ---------------- layer 1: on-the-fly edge weights + fused matmul -----------
// w_e = leaky((seW[my] + deW[opp]) / (deg[my] + deg[opp])); agg = sum f*r*w.
// Inner loop: explicit 4-edge batch per half for MLP.
__global__ void __launch_bounds__(WPB * 32) k_l1(
        const int2* __restrict__ adjAll, const int* __restrict__ rowAll,
        int rowStride,
        const float* __restrict__ myDeWAll, const float* __restrict__ oppDeWAll,
        const float2* __restrict__ drMyAll, const float2* __restrict__ drOppAll,
        const float* __restrict__ oppF, int nOpp,
        const float* __restrict__ Wn, float* __restrict__ outp, int n) {
    int t = blockIdx.y;
    size_t eoff = (t > 0 ? (size_t)EBC : 0) + (t > 1 ? (size_t)ECC : 0);
    const int2* adj = adjAll + eoff;
    const int* row = rowAll + t * rowStride;
    const float* myDeW = myDeWAll + (size_t)t * n * DC;
    const float* oppDeW = oppDeWAll + (size_t)t * nOpp * DC;
    const float2* drMy = drMyAll + t * n;
    const float2* drOpp = drOppAll + t * nOpp;
    float wgt = (t == 0) ? 1.f : (t == 1 ? 0.5f : 0.25f);

    __shared__ float4 sWn[64 * 16];
    __shared__ float wrow[WPB][66];   // a[d] at index d + (d>>5)

    int tid = threadIdx.x;
    for (int i = tid; i < 1024; i += WPB * 32) sWn[i] = ((const float4*)Wn)[i];
    __syncthreads();

    int wid = tid >> 5, lane = tid & 31, l16 = lane & 15, half = lane >> 4;
    int nodeBase = (blockIdx.x * WPB + wid) * NPW;

    for (int nd = 0; nd < NPW; nd++) {
        int node = nodeBase + nd;
        if (node >= n) break;
        int s0 = row[node], s1 = row[node + 1];
        float md = drMy[node].x;
        float4 m = __ldg((const float4*)(myDeW + (size_t)node * DC) + l16);
        float4 a = make_float4(0.f, 0.f, 0.f, 0.f);
        int i = s0 + half;
        for (; i + 6 < s1; i += 8) {
            int2 ad0 = __ldg(adj + i);
            int2 ad1 = __ldg(adj + i + 2);
            int2 ad2 = __ldg(adj + i + 4);
            int2 ad3 = __ldg(adj + i + 6);
            float2 dr0 = __ldg(drOpp + ad0.y);
            float2 dr1 = __ldg(drOpp + ad1.y);
            float2 dr2 = __ldg(drOpp + ad2.y);
            float2 dr3 = __ldg(drOpp + ad3.y);
            float4 o0 = __ldg((const float4*)(oppDeW + (size_t)ad0.y * DC) + l16);
            float4 o1 = __ldg((const float4*)(oppDeW + (size_t)ad1.y * DC) + l16);
            float4 o2 = __ldg((const float4*)(oppDeW + (size_t)ad2.y * DC) + l16);
            float4 o3 = __ldg((const float4*)(oppDeW + (size_t)ad3.y * DC) + l16);
            float4 f0 = __ldg((const float4*)(oppF + (size_t)ad0.y * DC) + l16);
            float4 f1 = __ldg((const float4*)(oppF + (size_t)ad1.y * DC) + l16);
            float4 f2 = __ldg((const float4*)(oppF + (size_t)ad2.y * DC) + l16);
            float4 f3 = __ldg((const float4*)(oppF + (size_t)ad3.y * DC) + l16);
            float s0f = 1.f / (md + dr0.x);
            float s1f = 1.f / (md + dr1.x);
            float s2f = 1.f / (md + dr2.x);
            float s3f = 1.f / (md + dr3.x);
            float c0 = dr0.y, c1 = dr1.y, c2 = dr2.y, c3 = dr3.y;
            a.x += f0.x * c0 * lk((m.x + o0.x) * s0f) + f1.x * c1 * lk((m.x + o1.x) * s1f)
                 + f2.x * c2 * lk((m.x + o2.x) * s2f) + f3.x * c3 * lk((m.x + o3.x) * s3f);
            a.y += f0.y * c0 * lk((m.y + o0.y) * s0f) + f1.y * c1 * lk((m.y + o1.y) * s1f)
                 + f2.y * c2 * lk((m.y + o2.y) * s2f) + f3.y * c3 * lk((m.y + o3.y) * s3f);
            a.z += f0.z * c0 * lk((m.z + o0.z) * s0f) + f1.z * c1 * lk((m.z + o1.z) * s1f)
                 + f2.z * c2 * lk((m.z + o2.z) * s2f) + f3.z * c3 * lk((m.z + o3.z) * s3f);
            a.w += f0.w * c0 * lk((m.w + o0.w) * s0f) + f1.w * c1 * lk((m.w + o1.w) * s1f)
                 + f2.w * c2 * lk((m.w + o2.w) * s2f) + f3.w * c3 * lk((m.w + o3.w) * s3f);
        }
        for (; i < s1; i += 2) {
            int2 ad = __ldg(adj + i);
            float2 dro = __ldg(drOpp + ad.y);
            float s = 1.f / (md + dro.x);
            float4 o = __ldg((const float4*)(oppDeW + (size_t)ad.y * DC) + l16);
            float4 f = __ldg((const float4*)(oppF + (size_t)ad.y * DC) + l16);
            float r = dro.y;
            a.x += f.x * r * lk((m.x + o.x) * s);
            a.y += f.y * r * lk((m.y + o.y) * s);
            a.z += f.z * r * lk((m.z + o.z) * s);
            a.w += f.w * r * lk((m.w + o.w) * s);
        }
        a.x += __shfl_xor_sync(0xffffffffu, a.x, 16);
        a.y += __shfl_xor_sync(0xffffffffu, a.y, 16);
        a.z += __shfl_xor_sync(0xffffffffu, a.z, 16);
        a.w += __shfl_xor_sync(0xffffffffu, a.w, 16);
        if (half == 0) {
            int p = l16 * 4;
            wrow[wid][p + (p >> 5)] = a.x;
            wrow[wid][p + 1 + ((p + 1) >> 5)] = a.y;
            wrow[wid][p + 2 + ((p + 2) >> 5)] = a.z;
            wrow[wid][p + 3 + ((p + 3) >> 5)] = a.w;
        }
        __syncwarp();

        const float* wr = &wrow[wid][half * 33];
        const float4* Wh = sWn + half * 32 * 16;
        float4 acc = make_float4(0.f, 0.f, 0.f, 0.f);
#pragma unroll
        for (int d2 = 0; d2 < 32; d2++) {
            float s = wr[d2];
            float4 w4 = Wh[d2 * 16 + l16];
            acc.x += s * w4.x; acc.y += s * w4.y;
            acc.z += s * w4.z; acc.w += s * w4.w;
        }
        acc.x += __shfl_xor_sync(0xffffffffu, acc.x, 16);
        acc.y += __shfl_xor_sync(0xffffffffu, acc.y, 16);
        acc.z += __shfl_xor_sync(0xffffffffu, acc.z, 16);
        acc.w += __shfl_xor_sync(0xffffffffu, acc.w, 16);
        __syncwarp();
        if (half == 0) {
            float rsn = drMy[node].y;
            float c = wgt * (1.f / 3.f);
            float4 ro;
            ro.x = lk(acc.x * rsn) * c;
            ro.y = lk(acc.y * rsn) * c;
            ro.z = lk(acc.z * rsn) * c;
            ro.w = lk(acc.w * rsn) * c;
            atomicAdd((float4*)(outp + (size_t)node * DC + l16 * 4), ro);
        }
    }
}

// ---------------- host orchestration ---------------------------------------
extern "C" void kernel_launch(void* const* d_in, const int* in_sizes, int n_in,
                              void* d_out, int out_size) {
    const float* user_emb = (const float*)d_in[0];
    const float* item_emb = (const float*)d_in[1];
    const float* e0 = (const float*)d_in[2];
    const float* e1 = (const float*)d_in[3];
    const float* e2 = (const float*)d_in[4];
    const float* nodeW = (const float*)d_in[5];
    const float* edgeW = (const float*)d_in[6];
    const int* Ua[3] = {(const int*)d_in[7], (const int*)d_in[9], (const int*)d_in[11]};
    const int* Va[3] = {(const int*)d_in[8], (const int*)d_in[10], (const int*)d_in[12]};
    float* out = (float*)d_out;
    float* outS = out;
    float* outD = out + (size_t)NUC * DC;

    float *srcB, *dstB, *se, *de;
    int *cntU, *cntV, *rowU, *rowV, *curU, *curV;
    float2 *drU, *drV;
    int2 *adjU, *adjV;
    cudaGetSymbolAddress((void**)&srcB, g_srcB);
    cudaGetSymbolAddress((void**)&dstB, g_dstB);
    cudaGetSymbolAddress((void**)&se, g_se);
    cudaGetSymbolAddress((void**)&de, g_de);
    cudaGetSymbolAddress((void**)&cntU, g_cntU);
    cudaGetSymbolAddress((void**)&cntV, g_cntV);
    cudaGetSymbolAddress((void**)&rowU, g_rowU);
    cudaGetSymbolAddress((void**)&rowV, g_rowV);
    cudaGetSymbolAddress((void**)&curU, g_curU);
    cudaGetSymbolAddress((void**)&curV, g_curV);
    cudaGetSymbolAddress((void**)&drU, g_drU);
    cudaGetSymbolAddress((void**)&drV, g_drV);
    cudaGetSymbolAddress((void**)&adjU, g_adjU);
    cudaGetSymbolAddress((void**)&adjV, g_adjV);

    const int Ecnt[3] = {EBC, ECC, EPC};
    const float Asc = 0.0045f;
    const float* Wn0 = nodeW;
    const float* Wn1 = nodeW + (size_t)DC * DC;
    const float* We0 = edgeW;

    // output accumulator init (pre-scaled by 1/3) + zero nxt buffers
    k_init<<<(NUC * DC / 4 + 255) / 256, 256>>>((const float4*)user_emb,
                                                Asc / 3.f, (float4*)outS, NUC * DC / 4);
    k_init<<<(NIC * DC / 4 + 255) / 256, 256>>>((const float4*)item_emb,
                                                Asc / 3.f, (float4*)outD, NIC * DC / 4);
    cudaMemsetAsync(srcB, 0, (size_t)NUC * DC * sizeof(float));
    cudaMemsetAsync(dstB, 0, (size_t)NIC * DC * sizeof(float));

    // CSR build
    cudaMemsetAsync(cntU, 0, 3 * NUC * sizeof(int));
    cudaMemsetAsync(cntV, 0, 3 * NIC * sizeof(int));
    for (int t = 0; t < 3; t++)
        k_hist<<<(Ecnt[t] + 255) / 256, 256>>>(Ua[t], Va[t], Ecnt[t],
                                               cntU + t * NUC, cntV + t * NIC);
    k_deg<<<(3 * NUC + 255) / 256, 256>>>(cntU, drU, 3 * NUC);
    k_deg<<<(3 * NIC + 255) / 256, 256>>>(cntV, drV, 3 * NIC);
    k_scan6<<<6, 1024>>>(cntU, cntV, rowU, rowV, curU, curV);
    {
        size_t eo = 0;
        for (int t = 0; t < 3; t++) {
            k_fill<<<(Ecnt[t] + 255) / 256, 256>>>(Ua[t], Va[t], Ecnt[t],
                                                   curU + t * NUC, curV + t * NIC,
                                                   adjU + eo, adjV + eo);
            eo += Ecnt[t];
        }
    }

    // layer 0 (3 types concurrent via gridDim.y)
    {
        dim3 gu((NUC + WPB * NPW - 1) / (WPB * NPW), 3);
        dim3 gv((NIC + WPB * NPW - 1) / (WPB * NPW), 3);
        k_l0<<<gu, WPB * 32>>>(e0, e1, e2, adjU, rowU, NUC + 1,
                               item_emb, Asc, drV, NIC, drU,
                               Wn0, We0, srcB, se, outS, NUC);
        k_l0<<<gv, WPB * 32>>>(e0, e1, e2, adjV, rowV, NIC + 1,
                               user_emb, Asc, drU, NUC, drV,
                               Wn0, We0, dstB, de, outD, NIC);
    }

    // layer 1 (edge features recomputed on the fly; output accumulate only)
    {
        dim3 gu((NUC + WPB * NPW - 1) / (WPB * NPW), 3);
        dim3 gv((NIC + WPB * NPW - 1) / (WPB * NPW), 3);
        k_l1<<<gu, WPB * 32>>>(adjU, rowU, NUC + 1, se, de, drU, drV,
                               dstB, NIC, Wn1, outS, NUC);
        k_l1<<<gv, WPB * 32>>>(adjV, rowV, NIC + 1, de, se, drV, drU,
                               srcB, NUC, Wn1, outD, NIC);
    }
}